// round 15
// baseline (speedup 1.0000x reference)
#include <cuda_runtime.h>

#define B 32
#define NN 128
#define DW 135
#define OBS 7
#define F 64
#define OD 4

// -------- device scratch (no allocations allowed) --------
__device__ __align__(16) float g_norm[B][NN];
__device__ float g_bmax[B];
__device__ __align__(16) float g_c[B][NN][F];      // c[j][f], f<63 valid, [63]=0
__device__ __align__(16) float g_cur[2][B][NN][F];
__device__ __align__(16) float g_edge[B][NN][F];
__device__ __align__(16) float g_P[B][OD];
__device__ __align__(16) float g_A[B][NN][OD];
__device__ __align__(16) float g_C[B][NN][OD];

// ---------------- K1: norm + per-batch max + c[j] + init_emb ----------------
__global__ void __launch_bounds__(128) k1_init(const float* __restrict__ obs,
                                               const float* __restrict__ Wi,
                                               const float* __restrict__ Wee) {
    int b = blockIdx.x;
    int j = threadIdx.x;              // node index 0..127
    __shared__ float sWi[F * OBS];
    __shared__ float sWee[63 * OBS];
    __shared__ int s_cnt[128];
    for (int t = j; t < F * OBS; t += 128) sWi[t] = Wi[t];
    for (int t = j; t < 63 * OBS; t += 128) {
        int f = t / OBS, k = t % OBS;
        sWee[t] = Wee[f * 8 + 1 + k];
    }
    __syncthreads();

    const float* ob = obs + (size_t)b * NN * DW;

    int cnt = 0;
#pragma unroll 8
    for (int i = 0; i < NN; i++)
        cnt += (ob[i * DW + OBS + j] != 0.0f);
    if (cnt == 0) cnt = 1;
    g_norm[b][j] = (float)cnt;
    s_cnt[j] = cnt;

    float nf[OBS];
#pragma unroll
    for (int k = 0; k < OBS; k++) nf[k] = ob[j * DW + k];

#pragma unroll 4
    for (int f = 0; f < F; f++) {
        float a = 0.f;
#pragma unroll
        for (int k = 0; k < OBS; k++) a = fmaf(nf[k], sWi[f * OBS + k], a);
        g_cur[0][b][j][f] = fmaxf(a, 0.f);
    }
#pragma unroll 4
    for (int f = 0; f < 63; f++) {
        float a = 0.f;
#pragma unroll
        for (int k = 0; k < OBS; k++) a = fmaf(nf[k], sWee[f * OBS + k], a);
        g_c[b][j][f] = a;
    }
    g_c[b][j][63] = 0.f;

    __syncthreads();
#pragma unroll
    for (int s = 64; s > 0; s >>= 1) {
        if (j < s) s_cnt[j] = max(s_cnt[j], s_cnt[j + s]);
        __syncthreads();
    }
    if (j == 0) g_bmax[b] = (float)s_cnt[0];
}

// ---------------- K2: edge aggregation + edge_emb ----------------
#define K2_NPB 8
#define K2_SMEM_FLOATS (8192 + 1024 + 4160 + 512 + 64 + 33)
#define K2_SMEM_BYTES  (K2_SMEM_FLOATS * 4)
__global__ void __launch_bounds__(512) k2_edge(const float* __restrict__ obs,
                                               const float* __restrict__ Wee,
                                               const float* __restrict__ Wef) {
    extern __shared__ float sm2[];
    float* s_c   = sm2;
    float* s_adj = s_c + 8192;
    float* s_WT  = s_adj + 1024;    // [k][f] stride 65
    float* s_x   = s_WT + 4160;
    float* s_w0  = s_x + 512;
    float* s_red = s_w0 + 64;

    int b = blockIdx.y;
    int itile = blockIdx.x;
    int tid = threadIdx.x;
    int f = tid & 63, q = tid >> 6;
    int i = itile * K2_NPB + q;

    const float* ob = obs + (size_t)b * NN * DW;

    {
        const float4* src = (const float4*)&g_c[b][0][0];
        float4* dst = (float4*)s_c;
        for (int t = tid; t < 2048; t += 512) dst[t] = src[t];
    }
    for (int t = tid; t < K2_NPB * NN; t += 512) {
        int il = t >> 7, j = t & 127;
        s_adj[t] = ob[(itile * K2_NPB + il) * DW + OBS + j];
    }
    for (int t = tid; t < F * F; t += 512) {
        int ff = t >> 6, k = t & 63;
        s_WT[k * 65 + ff] = Wef[t];
    }
    if (tid < F) s_w0[tid] = (tid < 63) ? Wee[tid * 8] : 0.f;
    if (tid < 32) s_red[tid] = g_bmax[tid];
    __syncthreads();
    if (tid == 0) {
        float m = s_red[0];
        for (int t = 1; t < 32; t++) m = fmaxf(m, s_red[t]);
        s_red[32] = m;
    }
    __syncthreads();

    float w0 = s_w0[f];
    float s = 0.f;
    const float* arow = &s_adj[q * 128];
#pragma unroll 8
    for (int j = 0; j < NN; j++) {
        float a = arow[j];
        float e = fmaxf(fmaf(a, w0, s_c[j * 64 + f]), 0.f);
        s += (a != 0.f) ? e : 0.f;
    }
    float nrm = g_norm[b][i];
    float mx = s_red[32];
    s_x[q * 64 + f] = (f < 63) ? (s / nrm) : (nrm / mx);
    __syncthreads();

    float acc = 0.f;
#pragma unroll 8
    for (int k = 0; k < F; k++) acc = fmaf(s_x[q * 64 + k], s_WT[k * 65 + f], acc);
    g_edge[b][i][f] = fmaxf(acc, 0.f);
}

// ---------------- K3: one message-passing layer, 4x4 register tiles ----------------
// 128 threads = 4 warps. lane = lf*8+ln: lf=lane>>3 (feat quad), ln=lane&7 (node quad).
// Thread tile: 4 nodes (n_base=4*ln) x 4 feats (f_base = w*16 + lf*4).
// Block = 32 nodes, all 64 output feats. Grid = (4, B) = 128 blocks.
#define WS 68      // weight / dense-cur row stride
#define TS 36      // transposed activation row stride
#define KR 130     // rows incl. 2 pad rows for prefetch overrun

// floats: Wm 130*68 | Wu 130*68 | cur 130*68 | adjT 130*36 | buf1 130*36 | buf2 130*36 | inv 32
#define K3_SMEM_FLOATS (KR * WS * 3 + KR * TS * 3 + 32)
#define K3_SMEM_BYTES  (K3_SMEM_FLOATS * 4)

__device__ __forceinline__ void fma4v(float4& acc, float xs, const float4& wv) {
    acc.x = fmaf(xs, wv.x, acc.x);
    acc.y = fmaf(xs, wv.y, acc.y);
    acc.z = fmaf(xs, wv.z, acc.z);
    acc.w = fmaf(xs, wv.w, acc.w);
}

// One 128-k GEMM phase: acc[r][q] += A[k][nb+r] * W[k][fb+q]; A stride TS, W stride WS.
__device__ __forceinline__ void gemm128(const float* __restrict__ Ab,
                                        const float* __restrict__ Wb,
                                        float4& acc0, float4& acc1,
                                        float4& acc2, float4& acc3) {
    float4 x0 = *(const float4*)&Ab[0 * TS];
    float4 w0 = *(const float4*)&Wb[0 * WS];
    float4 x1 = *(const float4*)&Ab[1 * TS];
    float4 w1 = *(const float4*)&Wb[1 * WS];
#pragma unroll
    for (int k = 0; k < 128; k += 2) {
        float4 x2 = *(const float4*)&Ab[(k + 2) * TS];
        float4 w2 = *(const float4*)&Wb[(k + 2) * WS];
        float4 x3 = *(const float4*)&Ab[(k + 3) * TS];
        float4 w3 = *(const float4*)&Wb[(k + 3) * WS];
        fma4v(acc0, x0.x, w0); fma4v(acc1, x0.y, w0);
        fma4v(acc2, x0.z, w0); fma4v(acc3, x0.w, w0);
        fma4v(acc0, x1.x, w1); fma4v(acc1, x1.y, w1);
        fma4v(acc2, x1.z, w1); fma4v(acc3, x1.w, w1);
        x0 = x2; w0 = w2; x1 = x3; w1 = w3;
    }
}

__global__ void __launch_bounds__(128, 1) k3_layer(const float* __restrict__ obs,
                                                   const float* __restrict__ Wm,
                                                   const float* __restrict__ Wu,
                                                   int src, int dst) {
    extern __shared__ float sm[];
    float* s_Wm   = sm;                      // [k][f] stride WS
    float* s_Wu   = s_Wm + KR * WS;
    float* s_cur  = s_Wu + KR * WS;          // dense [j][f] stride WS (all 128 nodes)
    float* s_adjT = s_cur + KR * WS;         // [j][n] stride TS
    float* s_buf1 = s_adjT + KR * TS;        // rows 0..63 aggT, 64..127 edgeT
    float* s_buf2 = s_buf1 + KR * TS;        // rows 0..63 curT, 64..127 msgT
    float* s_inv  = s_buf2 + KR * TS;

    int b = blockIdx.y, tile = blockIdx.x;
    int tid = threadIdx.x;
    int w  = tid >> 5;
    int lane = tid & 31;
    int lf = lane >> 3, ln = lane & 7;
    int f_base = w * 16 + lf * 4;
    int n_base = ln * 4;
    int i0 = tile * 32;
    const float* ob = obs + (size_t)b * NN * DW;

    // ---- staging ----
    for (int t = tid; t < 8192; t += 128) {      // transpose both weights
        int ff = t >> 7, k = t & 127;
        s_Wm[k * WS + ff] = Wm[t];
        s_Wu[k * WS + ff] = Wu[t];
    }
    {
        const float4* src4 = (const float4*)&g_cur[src][b][0][0];
        for (int t = tid; t < 2048; t += 128) {  // dense cur, stride WS
            int j = t >> 4, q = t & 15;
            *(float4*)&s_cur[j * WS + q * 4] = src4[t];
        }
    }
    for (int t = tid; t < 2048; t += 128) {      // own-slice curT + edgeT
        int n = t >> 6, f = t & 63;
        s_buf2[f * TS + n] = g_cur[src][b][i0 + n][f];
        s_buf1[(64 + f) * TS + n] = g_edge[b][i0 + n][f];
    }
    for (int t = tid; t < 4096; t += 128) {      // adjT
        int n = t >> 7, j = t & 127;
        s_adjT[j * TS + n] = ob[(i0 + n) * DW + OBS + j];
    }
    if (tid < 32) s_inv[tid] = 1.0f / g_norm[b][i0 + tid];
    __syncthreads();

    // ---- phase 1: agg = adj @ cur / norm -> buf1 rows 0..63 (aggT) ----
    {
        float4 acc0 = {0, 0, 0, 0}, acc1 = {0, 0, 0, 0};
        float4 acc2 = {0, 0, 0, 0}, acc3 = {0, 0, 0, 0};
        gemm128(s_adjT + n_base, s_cur + f_base, acc0, acc1, acc2, acc3);
        float iv0 = s_inv[n_base + 0], iv1 = s_inv[n_base + 1];
        float iv2 = s_inv[n_base + 2], iv3 = s_inv[n_base + 3];
        acc0.x *= iv0; acc0.y *= iv0; acc0.z *= iv0; acc0.w *= iv0;
        acc1.x *= iv1; acc1.y *= iv1; acc1.z *= iv1; acc1.w *= iv1;
        acc2.x *= iv2; acc2.y *= iv2; acc2.z *= iv2; acc2.w *= iv2;
        acc3.x *= iv3; acc3.y *= iv3; acc3.z *= iv3; acc3.w *= iv3;
        // transpose-store: buf1[(f_base+q)*TS + n_base+r]
        float* o0 = &s_buf1[(f_base + 0) * TS + n_base];
        float* o1 = &s_buf1[(f_base + 1) * TS + n_base];
        float* o2 = &s_buf1[(f_base + 2) * TS + n_base];
        float* o3 = &s_buf1[(f_base + 3) * TS + n_base];
        o0[0] = acc0.x; o0[1] = acc1.x; o0[2] = acc2.x; o0[3] = acc3.x;
        o1[0] = acc0.y; o1[1] = acc1.y; o1[2] = acc2.y; o1[3] = acc3.y;
        o2[0] = acc0.z; o2[1] = acc1.z; o2[2] = acc2.z; o2[3] = acc3.z;
        o3[0] = acc0.w; o3[1] = acc1.w; o3[2] = acc2.w; o3[3] = acc3.w;
    }
    __syncthreads();

    // ---- phase 2: msg = relu([agg, edge] @ Wm^T) -> buf2 rows 64..127 (msgT) ----
    {
        float4 acc0 = {0, 0, 0, 0}, acc1 = {0, 0, 0, 0};
        float4 acc2 = {0, 0, 0, 0}, acc3 = {0, 0, 0, 0};
        gemm128(s_buf1 + n_base, s_Wm + f_base, acc0, acc1, acc2, acc3);
        float* o0 = &s_buf2[(64 + f_base + 0) * TS + n_base];
        float* o1 = &s_buf2[(64 + f_base + 1) * TS + n_base];
        float* o2 = &s_buf2[(64 + f_base + 2) * TS + n_base];
        float* o3 = &s_buf2[(64 + f_base + 3) * TS + n_base];
        o0[0] = fmaxf(acc0.x, 0.f); o0[1] = fmaxf(acc1.x, 0.f);
        o0[2] = fmaxf(acc2.x, 0.f); o0[3] = fmaxf(acc3.x, 0.f);
        o1[0] = fmaxf(acc0.y, 0.f); o1[1] = fmaxf(acc1.y, 0.f);
        o1[2] = fmaxf(acc2.y, 0.f); o1[3] = fmaxf(acc3.y, 0.f);
        o2[0] = fmaxf(acc0.z, 0.f); o2[1] = fmaxf(acc1.z, 0.f);
        o2[2] = fmaxf(acc2.z, 0.f); o2[3] = fmaxf(acc3.z, 0.f);
        o3[0] = fmaxf(acc0.w, 0.f); o3[1] = fmaxf(acc1.w, 0.f);
        o3[2] = fmaxf(acc2.w, 0.f); o3[3] = fmaxf(acc3.w, 0.f);
    }
    __syncthreads();

    // ---- phase 3: cur' = relu([cur, msg] @ Wu^T) -> global ----
    {
        float4 acc0 = {0, 0, 0, 0}, acc1 = {0, 0, 0, 0};
        float4 acc2 = {0, 0, 0, 0}, acc3 = {0, 0, 0, 0};
        gemm128(s_buf2 + n_base, s_Wu + f_base, acc0, acc1, acc2, acc3);
        acc0.x = fmaxf(acc0.x, 0.f); acc0.y = fmaxf(acc0.y, 0.f);
        acc0.z = fmaxf(acc0.z, 0.f); acc0.w = fmaxf(acc0.w, 0.f);
        acc1.x = fmaxf(acc1.x, 0.f); acc1.y = fmaxf(acc1.y, 0.f);
        acc1.z = fmaxf(acc1.z, 0.f); acc1.w = fmaxf(acc1.w, 0.f);
        acc2.x = fmaxf(acc2.x, 0.f); acc2.y = fmaxf(acc2.y, 0.f);
        acc2.z = fmaxf(acc2.z, 0.f); acc2.w = fmaxf(acc2.w, 0.f);
        acc3.x = fmaxf(acc3.x, 0.f); acc3.y = fmaxf(acc3.y, 0.f);
        acc3.z = fmaxf(acc3.z, 0.f); acc3.w = fmaxf(acc3.w, 0.f);
        *(float4*)&g_cur[dst][b][i0 + n_base + 0][f_base] = acc0;
        *(float4*)&g_cur[dst][b][i0 + n_base + 1][f_base] = acc1;
        *(float4*)&g_cur[dst][b][i0 + n_base + 2][f_base] = acc2;
        *(float4*)&g_cur[dst][b][i0 + n_base + 3][f_base] = acc3;
    }
}

// ---------------- K4: pool + readout precompute ----------------
__global__ void __launch_bounds__(128) k4_pool(const float* __restrict__ Wp,
                                               const float* __restrict__ Wr,
                                               const float* __restrict__ br,
                                               int src) {
    int b = blockIdx.x;
    int tid = threadIdx.x;
    __shared__ float s_part[128];
    __shared__ float s_mean[F];
    __shared__ float s_rp[F];
    __shared__ float s_Wr[OD * 3 * F];   // 768

    for (int t = tid; t < OD * 3 * F; t += 128) s_Wr[t] = Wr[t];

    {
        int f = tid & 63, h = tid >> 6;
        float acc = 0.f;
        for (int i = h; i < NN; i += 2) acc += g_cur[src][b][i][f];
        s_part[tid] = acc;
    }
    __syncthreads();
    if (tid < F) s_mean[tid] = (s_part[tid] + s_part[tid + 64]) * (1.0f / NN);
    __syncthreads();
    if (tid < F) {
        float hp = 0.f;
#pragma unroll 8
        for (int k = 0; k < F; k++) hp = fmaf(s_mean[k], Wp[tid * 64 + k], hp);
        s_rp[tid] = fmaxf(hp, 0.f);
    }
    __syncthreads();
    if (tid < OD) {
        float p = br[tid];
#pragma unroll 8
        for (int f = 0; f < F; f++) p = fmaf(s_rp[f], s_Wr[tid * 192 + f], p);
        g_P[b][tid] = p;
    }
    int i = tid;
    float a[OD] = {0.f, 0.f, 0.f, 0.f};
    float c[OD] = {0.f, 0.f, 0.f, 0.f};
#pragma unroll 4
    for (int k = 0; k < F; k++) {
        float r = fmaxf(g_cur[src][b][i][k], 0.f);
#pragma unroll
        for (int o = 0; o < OD; o++) {
            a[o] = fmaf(r, s_Wr[o * 192 + 64 + k], a[o]);
            c[o] = fmaf(r, s_Wr[o * 192 + 128 + k], c[o]);
        }
    }
#pragma unroll
    for (int o = 0; o < OD; o++) {
        g_A[b][i][o] = a[o];
        g_C[b][i][o] = c[o];
    }
}

// ---------------- K5: output writer ----------------
__global__ void __launch_bounds__(512) k5_out(float* __restrict__ out) {
    int b = blockIdx.y;
    int tid = threadIdx.x;
    int j = tid & 127, iq = tid >> 7;
    int i = blockIdx.x * 4 + iq;
    float4 P = *(const float4*)&g_P[b][0];
    float4 A = *(const float4*)&g_A[b][i][0];
    float4 C = *(const float4*)&g_C[b][j][0];
    float4 r;
    r.x = P.x + A.x + C.x;
    r.y = P.y + A.y + C.y;
    r.z = P.z + A.z + C.z;
    r.w = P.w + A.w + C.w;
    ((float4*)out)[((size_t)b * NN + i) * NN + j] = r;
}

// ---------------- launch ----------------
extern "C" void kernel_launch(void* const* d_in, const int* in_sizes, int n_in,
                              void* d_out, int out_size) {
    const float* obs = (const float*)d_in[0];
    const float* Wi  = (const float*)d_in[1];
    const float* Wee = (const float*)d_in[2];
    const float* Wef = (const float*)d_in[3];
    const float* Wm  = (const float*)d_in[4];
    const float* Wu  = (const float*)d_in[5];
    const float* Wp  = (const float*)d_in[6];
    const float* Wr  = (const float*)d_in[7];
    const float* br  = (const float*)d_in[8];

    static int attr_done = 0;
    if (!attr_done) {
        cudaFuncSetAttribute(k3_layer, cudaFuncAttributeMaxDynamicSharedMemorySize, K3_SMEM_BYTES);
        cudaFuncSetAttribute(k2_edge, cudaFuncAttributeMaxDynamicSharedMemorySize, K2_SMEM_BYTES);
        attr_done = 1;
    }

    k1_init<<<B, 128>>>(obs, Wi, Wee);
    k2_edge<<<dim3(NN / K2_NPB, B), 512, K2_SMEM_BYTES>>>(obs, Wee, Wef);

    const int LW = F * 2 * F;  // 8192 floats per layer
    k3_layer<<<dim3(4, B), 128, K3_SMEM_BYTES>>>(obs, Wm + 0 * LW, Wu + 0 * LW, 0, 1);
    k3_layer<<<dim3(4, B), 128, K3_SMEM_BYTES>>>(obs, Wm + 1 * LW, Wu + 1 * LW, 1, 0);
    k3_layer<<<dim3(4, B), 128, K3_SMEM_BYTES>>>(obs, Wm + 2 * LW, Wu + 2 * LW, 0, 1);

    k4_pool<<<B, 128>>>(Wp, Wr, br, 1);
    k5_out<<<dim3(NN / 4, B), 512>>>((float*)d_out);
}

// round 16
// speedup vs baseline: 1.2923x; 1.2923x over previous
#include <cuda_runtime.h>

#define B 32
#define NN 128
#define DW 135
#define OBS 7
#define F 64
#define OD 4

// -------- device scratch --------
__device__ __align__(16) float g_norm[B][NN];
__device__ float g_blkmax[128];
__device__ __align__(16) float g_c[B][NN][F];
__device__ __align__(16) float g_cur[2][B][NN][F];
__device__ __align__(16) float g_edge[B][NN][F];
__device__ __align__(16) float g_P[B][OD];
__device__ __align__(16) float g_A[B][NN][OD];
__device__ __align__(16) float g_C[B][NN][OD];

// global barrier state (reset by k0 each call)
__device__ int g_barc[8];
__device__ volatile int g_barg[8];

__global__ void k0_reset() {
    if (threadIdx.x < 8) { g_barc[threadIdx.x] = 0; g_barg[threadIdx.x] = 0; }
}

__device__ __forceinline__ void gbar(int ph) {
    __syncthreads();
    if (threadIdx.x == 0) {
        __threadfence();
        int t = atomicAdd(&g_barc[ph], 1);
        if (t == (int)gridDim.x - 1) {
            g_barg[ph] = 1;
        } else {
            while (g_barg[ph] == 0) __nanosleep(64);
        }
        __threadfence();
    }
    __syncthreads();
}

// smem layout (floats):
//  s_Wm 8704 | s_Wu 8704 | s_cur 8192 | s_adj 4096 | s_edge 2048 | s_agg 2048 | s_msg 2048 | s_inv 32
#define SM_FLOATS (8704 * 2 + 8192 + 4096 + 2048 * 3 + 32)
#define SM_BYTES  (SM_FLOATS * 4)

__global__ void __launch_bounds__(256, 1) mega(const float* __restrict__ obs,
                                               const float* __restrict__ Wi,
                                               const float* __restrict__ Wee,
                                               const float* __restrict__ Wef,
                                               const float* __restrict__ Wm,
                                               const float* __restrict__ Wu,
                                               const float* __restrict__ Wp,
                                               const float* __restrict__ Wr,
                                               const float* __restrict__ br,
                                               float* __restrict__ out) {
    extern __shared__ float sm[];
    float* s_Wm   = sm;
    float* s_Wu   = sm + 8704;
    float* s_cur  = sm + 17408;
    float* s_adj  = sm + 25600;   // [32][128], persists P2..P4
    float* s_edge = sm + 29696;   // [32][64], persists
    float* s_agg  = sm + 31744;
    float* s_msg  = sm + 33792;
    float* s_inv  = sm + 35840;   // [32], persists

    int blk = blockIdx.x;
    int tid = threadIdx.x;
    int b  = blk >> 2;
    int i0 = (blk & 3) * 32;
    const float* ob = obs + (size_t)b * NN * DW;

    // ================= P0: k1 (norm, c, init_emb) =================
    {
        float* s1_Wi  = sm;          // 448
        float* s1_Wee = sm + 448;    // 441
        float* s1_cnt = sm + 896;    // 32

        for (int t = tid; t < F * OBS; t += 256) s1_Wi[t] = Wi[t];
        for (int t = tid; t < 63 * OBS; t += 256) {
            int f = t / OBS, k = t % OBS;
            s1_Wee[t] = Wee[f * 8 + 1 + k];
        }
        __syncthreads();

        int node = i0 + (tid & 31);
        int part = tid >> 5;   // 0..7

        if (part == 0) {
            int cnt = 0;
#pragma unroll 8
            for (int i = 0; i < NN; i++)
                cnt += (ob[i * DW + OBS + node] != 0.0f);
            if (cnt == 0) cnt = 1;
            g_norm[b][node] = (float)cnt;
            s1_cnt[tid] = (float)cnt;
        }

        float nf[OBS];
#pragma unroll
        for (int k = 0; k < OBS; k++) nf[k] = ob[node * DW + k];

        int f0 = part * 8;
#pragma unroll
        for (int f = f0; f < f0 + 8; f++) {
            float a = 0.f;
#pragma unroll
            for (int k = 0; k < OBS; k++) a = fmaf(nf[k], s1_Wi[f * OBS + k], a);
            g_cur[0][b][node][f] = fmaxf(a, 0.f);
        }
        int fe = (part == 7) ? 63 : f0 + 8;
        for (int f = f0; f < fe; f++) {
            float a = 0.f;
#pragma unroll
            for (int k = 0; k < OBS; k++) a = fmaf(nf[k], s1_Wee[f * OBS + k], a);
            g_c[b][node][f] = a;
        }
        if (part == 7) g_c[b][node][63] = 0.f;

        __syncthreads();
        if (tid == 0) {
            float m = s1_cnt[0];
            for (int t = 1; t < 32; t++) m = fmaxf(m, s1_cnt[t]);
            g_blkmax[blk] = m;
        }
    }
    gbar(0);

    // ================= P1: k2 (edge aggregation + edge_emb) =================
    {
        float* s2_c   = sm;           // 8192
        float* s2_adj = sm + 8192;    // 4096 [32][128]
        float* s2_WT  = sm + 12288;   // 4160 [k][f] stride 65
        float* s2_x   = sm + 16448;   // 2048 [32][64]
        float* s2_w0  = sm + 18496;   // 64
        float* s2_mx  = sm + 18560;   // 1

        {
            const float4* src4 = (const float4*)&g_c[b][0][0];
            float4* dst4 = (float4*)s2_c;
            for (int t = tid; t < 2048; t += 256) dst4[t] = src4[t];
        }
        for (int t = tid; t < 4096; t += 256) {
            int n = t >> 7, j = t & 127;
            s2_adj[t] = ob[(i0 + n) * DW + OBS + j];
        }
        for (int t = tid; t < F * F; t += 256) {
            int ff = t >> 6, k = t & 63;
            s2_WT[k * 65 + ff] = Wef[t];
        }
        if (tid < F) s2_w0[tid] = (tid < 63) ? Wee[tid * 8] : 0.f;
        if (tid < 128) s2_x[tid] = g_blkmax[tid];   // temp reduce buffer
        __syncthreads();
        if (tid == 0) {
            float m = s2_x[0];
            for (int t = 1; t < 128; t++) m = fmaxf(m, s2_x[t]);
            s2_mx[0] = m;
        }
        __syncthreads();
        float mx = s2_mx[0];
        __syncthreads();   // ensure all have read mx before s2_x overwritten

        int f = tid & 63, q = tid >> 6;
        float w0 = s2_w0[f];
        for (int n = q; n < 32; n += 4) {
            float s = 0.f;
            const float* arow = &s2_adj[n * 128];
#pragma unroll 8
            for (int j = 0; j < NN; j++) {
                float a = arow[j];
                float e = fmaxf(fmaf(a, w0, s2_c[j * 64 + f]), 0.f);
                s += (a != 0.f) ? e : 0.f;
            }
            float nrm = g_norm[b][i0 + n];
            s2_x[n * 64 + f] = (f < 63) ? (s / nrm) : (nrm / mx);
        }
        __syncthreads();
        for (int n = q; n < 32; n += 4) {
            float acc = 0.f;
#pragma unroll 8
            for (int k = 0; k < F; k++)
                acc = fmaf(s2_x[n * 64 + k], s2_WT[k * 65 + f], acc);
            g_edge[b][i0 + n][f] = fmaxf(acc, 0.f);
        }
    }
    gbar(1);

    // ================= P2-P4: three message-passing layers (R5 body) =================
    {
        int fg = tid & 15;
        int ns = tid >> 4;
        int il0 = ns * 2, il1 = il0 + 1;

        for (int l = 0; l < 3; l++) {
            const float* Wl = Wm + l * 8192;
            const float* Ul = Wu + l * 8192;
            int src = (l == 1) ? 1 : 0;
            int dst = (l == 1) ? 0 : 1;

            // staging
            for (int t = tid; t < 8192; t += 256) {
                int ff = t >> 7, k = t & 127;
                s_Wm[k * 68 + ff] = Wl[t];
                s_Wu[k * 68 + ff] = Ul[t];
            }
            {
                const float4* src4 = (const float4*)&g_cur[src][b][0][0];
                float4* dst4 = (float4*)s_cur;
                for (int t = tid; t < 2048; t += 256) dst4[t] = src4[t];
            }
            if (l == 0) {
                for (int t = tid; t < 4096; t += 256) {
                    int r = t >> 7, j = t & 127;
                    s_adj[t] = ob[(i0 + r) * DW + OBS + j];
                }
                const float4* es = (const float4*)&g_edge[b][i0][0];
                float4* ed = (float4*)s_edge;
                for (int t = tid; t < 512; t += 256) ed[t] = es[t];
                if (tid < 32) s_inv[tid] = 1.0f / g_norm[b][i0 + tid];
            }
            __syncthreads();

            // ---- agg = adj @ cur / norm ----
            {
                float4 a0 = {0, 0, 0, 0}, a1 = {0, 0, 0, 0};
                const float* ar0 = &s_adj[il0 * 128];
                const float* ar1 = &s_adj[il1 * 128];
#pragma unroll 8
                for (int j = 0; j < NN; j++) {
                    float4 c = *(const float4*)&s_cur[j * 64 + fg * 4];
                    float v0 = ar0[j], v1 = ar1[j];
                    a0.x = fmaf(v0, c.x, a0.x); a0.y = fmaf(v0, c.y, a0.y);
                    a0.z = fmaf(v0, c.z, a0.z); a0.w = fmaf(v0, c.w, a0.w);
                    a1.x = fmaf(v1, c.x, a1.x); a1.y = fmaf(v1, c.y, a1.y);
                    a1.z = fmaf(v1, c.z, a1.z); a1.w = fmaf(v1, c.w, a1.w);
                }
                float i0v = s_inv[il0], i1v = s_inv[il1];
                a0.x *= i0v; a0.y *= i0v; a0.z *= i0v; a0.w *= i0v;
                a1.x *= i1v; a1.y *= i1v; a1.z *= i1v; a1.w *= i1v;
                *(float4*)&s_agg[il0 * 64 + fg * 4] = a0;
                *(float4*)&s_agg[il1 * 64 + fg * 4] = a1;
            }
            __syncthreads();

            // ---- msg = relu([agg, edge] @ Wm^T) ----
            {
                float4 m0 = {0, 0, 0, 0}, m1 = {0, 0, 0, 0};
#pragma unroll 8
                for (int k = 0; k < F; k++) {
                    float4 w1 = *(const float4*)&s_Wm[k * 68 + fg * 4];
                    float4 w2 = *(const float4*)&s_Wm[(F + k) * 68 + fg * 4];
                    float g0 = s_agg[il0 * 64 + k], g1 = s_agg[il1 * 64 + k];
                    float e0 = s_edge[il0 * 64 + k], e1 = s_edge[il1 * 64 + k];
                    m0.x = fmaf(g0, w1.x, fmaf(e0, w2.x, m0.x));
                    m0.y = fmaf(g0, w1.y, fmaf(e0, w2.y, m0.y));
                    m0.z = fmaf(g0, w1.z, fmaf(e0, w2.z, m0.z));
                    m0.w = fmaf(g0, w1.w, fmaf(e0, w2.w, m0.w));
                    m1.x = fmaf(g1, w1.x, fmaf(e1, w2.x, m1.x));
                    m1.y = fmaf(g1, w1.y, fmaf(e1, w2.y, m1.y));
                    m1.z = fmaf(g1, w1.z, fmaf(e1, w2.z, m1.z));
                    m1.w = fmaf(g1, w1.w, fmaf(e1, w2.w, m1.w));
                }
                m0.x = fmaxf(m0.x, 0.f); m0.y = fmaxf(m0.y, 0.f);
                m0.z = fmaxf(m0.z, 0.f); m0.w = fmaxf(m0.w, 0.f);
                m1.x = fmaxf(m1.x, 0.f); m1.y = fmaxf(m1.y, 0.f);
                m1.z = fmaxf(m1.z, 0.f); m1.w = fmaxf(m1.w, 0.f);
                *(float4*)&s_msg[il0 * 64 + fg * 4] = m0;
                *(float4*)&s_msg[il1 * 64 + fg * 4] = m1;
            }
            __syncthreads();

            // ---- cur' = relu([cur, msg] @ Wu^T) ----
            {
                float4 u0 = {0, 0, 0, 0}, u1 = {0, 0, 0, 0};
                const float* c0 = &s_cur[(i0 + il0) * 64];
                const float* c1 = &s_cur[(i0 + il1) * 64];
#pragma unroll 8
                for (int k = 0; k < F; k++) {
                    float4 w1 = *(const float4*)&s_Wu[k * 68 + fg * 4];
                    float4 w2 = *(const float4*)&s_Wu[(F + k) * 68 + fg * 4];
                    float cv0 = c0[k], cv1 = c1[k];
                    float mv0 = s_msg[il0 * 64 + k], mv1 = s_msg[il1 * 64 + k];
                    u0.x = fmaf(cv0, w1.x, fmaf(mv0, w2.x, u0.x));
                    u0.y = fmaf(cv0, w1.y, fmaf(mv0, w2.y, u0.y));
                    u0.z = fmaf(cv0, w1.z, fmaf(mv0, w2.z, u0.z));
                    u0.w = fmaf(cv0, w1.w, fmaf(mv0, w2.w, u0.w));
                    u1.x = fmaf(cv1, w1.x, fmaf(mv1, w2.x, u1.x));
                    u1.y = fmaf(cv1, w1.y, fmaf(mv1, w2.y, u1.y));
                    u1.z = fmaf(cv1, w1.z, fmaf(mv1, w2.z, u1.z));
                    u1.w = fmaf(cv1, w1.w, fmaf(mv1, w2.w, u1.w));
                }
                u0.x = fmaxf(u0.x, 0.f); u0.y = fmaxf(u0.y, 0.f);
                u0.z = fmaxf(u0.z, 0.f); u0.w = fmaxf(u0.w, 0.f);
                u1.x = fmaxf(u1.x, 0.f); u1.y = fmaxf(u1.y, 0.f);
                u1.z = fmaxf(u1.z, 0.f); u1.w = fmaxf(u1.w, 0.f);
                *(float4*)&g_cur[dst][b][i0 + il0][fg * 4] = u0;
                *(float4*)&g_cur[dst][b][i0 + il1][fg * 4] = u1;
            }
            gbar(2 + l);
        }
    }

    // ================= P5: k4 (pool + readout precompute), blocks 0..31 =================
    if (blk < 32) {
        int bb = blk;
        float* s_part = sm;          // 256
        float* s_mean = sm + 256;    // 64
        float* s_rp   = sm + 320;    // 64
        float* s_Wr   = sm + 384;    // 768

        for (int t = tid; t < OD * 3 * F; t += 256) s_Wr[t] = Wr[t];
        {
            int f = tid & 63, h = tid >> 6;
            float acc = 0.f;
            for (int i = h; i < NN; i += 4) acc += g_cur[1][bb][i][f];
            s_part[tid] = acc;
        }
        __syncthreads();
        if (tid < F)
            s_mean[tid] = (s_part[tid] + s_part[tid + 64] + s_part[tid + 128] + s_part[tid + 192]) * (1.0f / NN);
        __syncthreads();
        if (tid < F) {
            float hp = 0.f;
#pragma unroll 8
            for (int k = 0; k < F; k++) hp = fmaf(s_mean[k], Wp[tid * 64 + k], hp);
            s_rp[tid] = fmaxf(hp, 0.f);
        }
        __syncthreads();
        if (tid < OD) {
            float p = br[tid];
#pragma unroll 8
            for (int f = 0; f < F; f++) p = fmaf(s_rp[f], s_Wr[tid * 192 + f], p);
            g_P[bb][tid] = p;
        }
        if (tid < 128) {
            int i = tid;
            float a[OD] = {0.f, 0.f, 0.f, 0.f};
            float c[OD] = {0.f, 0.f, 0.f, 0.f};
#pragma unroll 4
            for (int k = 0; k < F; k++) {
                float r = fmaxf(g_cur[1][bb][i][k], 0.f);
#pragma unroll
                for (int o = 0; o < OD; o++) {
                    a[o] = fmaf(r, s_Wr[o * 192 + 64 + k], a[o]);
                    c[o] = fmaf(r, s_Wr[o * 192 + 128 + k], c[o]);
                }
            }
#pragma unroll
            for (int o = 0; o < OD; o++) {
                g_A[bb][i][o] = a[o];
                g_C[bb][i][o] = c[o];
            }
        }
    }
    gbar(5);

    // ================= P6: k5 output writer =================
    {
        int j = tid & 127;
        int ih = tid >> 7;   // 0..1
        float4 Pv = *(const float4*)&g_P[b][0];
        float4 Cv = *(const float4*)&g_C[b][j][0];
        float4* out4 = (float4*)out;
#pragma unroll
        for (int ii = 0; ii < 16; ii++) {
            int i = i0 + ih * 16 + ii;
            float4 Av = *(const float4*)&g_A[b][i][0];
            float4 r;
            r.x = Pv.x + Av.x + Cv.x;
            r.y = Pv.y + Av.y + Cv.y;
            r.z = Pv.z + Av.z + Cv.z;
            r.w = Pv.w + Av.w + Cv.w;
            out4[((size_t)b * NN + i) * NN + j] = r;
        }
    }
}

// ---------------- launch ----------------
extern "C" void kernel_launch(void* const* d_in, const int* in_sizes, int n_in,
                              void* d_out, int out_size) {
    const float* obs = (const float*)d_in[0];
    const float* Wi  = (const float*)d_in[1];
    const float* Wee = (const float*)d_in[2];
    const float* Wef = (const float*)d_in[3];
    const float* Wm  = (const float*)d_in[4];
    const float* Wu  = (const float*)d_in[5];
    const float* Wp  = (const float*)d_in[6];
    const float* Wr  = (const float*)d_in[7];
    const float* br  = (const float*)d_in[8];

    static int attr_done = 0;
    if (!attr_done) {
        cudaFuncSetAttribute(mega, cudaFuncAttributeMaxDynamicSharedMemorySize, SM_BYTES);
        attr_done = 1;
    }

    k0_reset<<<1, 32>>>();
    mega<<<128, 256, SM_BYTES>>>(obs, Wi, Wee, Wef, Wm, Wu, Wp, Wr, br, (float*)d_out);
}

// round 17
// speedup vs baseline: 1.3583x; 1.0511x over previous
#include <cuda_runtime.h>

#define B 32
#define NN 128
#define DW 135
#define OBS 7
#define F 64
#define OD 4

// -------- device scratch --------
__device__ __align__(16) float g_norm[B][NN];
__device__ float g_blkmax[128];
__device__ __align__(16) float g_c[B][NN][F];
__device__ __align__(16) float g_cur[2][B][NN][F];
__device__ __align__(16) float g_edge[B][NN][F];
__device__ __align__(16) float g_A[B][NN][OD];   // includes folded P
__device__ __align__(16) float g_C[B][NN][OD];

// -------- self-resetting sense-reversal barriers (no per-launch init) --------
__device__ int          g_gcnt;          // zero-init at module load; resets itself
__device__ volatile int g_gflag;
__device__ int          g_bcnt[4][32 * 32];   // [slot][b*32] : 128B spacing
__device__ int          g_bflag[4][32 * 32];

__device__ __forceinline__ void gbar_global() {
    __syncthreads();
    if (threadIdx.x == 0) {
        __threadfence();
        int s = g_gflag;                       // capture sense BEFORE arriving
        int t = atomicAdd(&g_gcnt, 1);
        if (t == 127) {
            g_gcnt = 0;
            __threadfence();
            g_gflag = s ^ 1;
        } else {
            while (g_gflag == s) __nanosleep(32);
        }
        __threadfence();
    }
    __syncthreads();
}

__device__ __forceinline__ void gbar_batch(int b, int ph) {
    __syncthreads();
    if (threadIdx.x == 0) {
        __threadfence();
        volatile int* fl = (volatile int*)&g_bflag[ph][b * 32];
        int s = *fl;
        int t = atomicAdd(&g_bcnt[ph][b * 32], 1);
        if (t == 3) {
            g_bcnt[ph][b * 32] = 0;
            __threadfence();
            *fl = s ^ 1;
        } else {
            while (*fl == s) __nanosleep(32);
        }
        __threadfence();
    }
    __syncthreads();
}

// smem layout (floats):
//  s_Wm 8704 | s_Wu 8704 | s_cur 8192 | s_adj 4096 | s_edge 2048 | s_agg 2048 | s_msg 2048 | s_inv 32
#define SM_FLOATS (8704 * 2 + 8192 + 4096 + 2048 * 3 + 32)
#define SM_BYTES  (SM_FLOATS * 4)

__global__ void __launch_bounds__(256, 1) mega(const float* __restrict__ obs,
                                               const float* __restrict__ Wi,
                                               const float* __restrict__ Wee,
                                               const float* __restrict__ Wef,
                                               const float* __restrict__ Wm,
                                               const float* __restrict__ Wu,
                                               const float* __restrict__ Wp,
                                               const float* __restrict__ Wr,
                                               const float* __restrict__ br,
                                               float* __restrict__ out) {
    extern __shared__ float sm[];
    float* s_Wm   = sm;
    float* s_Wu   = sm + 8704;
    float* s_cur  = sm + 17408;
    float* s_adj  = sm + 25600;   // [32][128], persists through layers
    float* s_edge = sm + 29696;   // [32][64], persists
    float* s_agg  = sm + 31744;
    float* s_msg  = sm + 33792;
    float* s_inv  = sm + 35840;   // [32], persists

    int blk = blockIdx.x;
    int tid = threadIdx.x;
    int b  = blk >> 2;
    int i0 = (blk & 3) * 32;
    const float* ob = obs + (size_t)b * NN * DW;

    // ================= P0: norm, c, init_emb =================
    {
        float* s1_Wi  = sm;          // 448
        float* s1_Wee = sm + 448;    // 441
        float* s1_cnt = sm + 896;    // 32

        for (int t = tid; t < F * OBS; t += 256) s1_Wi[t] = Wi[t];
        for (int t = tid; t < 63 * OBS; t += 256) {
            int f = t / OBS, k = t % OBS;
            s1_Wee[t] = Wee[f * 8 + 1 + k];
        }
        __syncthreads();

        int node = i0 + (tid & 31);
        int part = tid >> 5;   // 0..7

        if (part == 0) {
            int cnt = 0;
#pragma unroll 8
            for (int i = 0; i < NN; i++)
                cnt += (ob[i * DW + OBS + node] != 0.0f);
            if (cnt == 0) cnt = 1;
            g_norm[b][node] = (float)cnt;
            s1_cnt[tid] = (float)cnt;
        }

        float nf[OBS];
#pragma unroll
        for (int k = 0; k < OBS; k++) nf[k] = ob[node * DW + k];

        int f0 = part * 8;
#pragma unroll
        for (int f = f0; f < f0 + 8; f++) {
            float a = 0.f;
#pragma unroll
            for (int k = 0; k < OBS; k++) a = fmaf(nf[k], s1_Wi[f * OBS + k], a);
            g_cur[0][b][node][f] = fmaxf(a, 0.f);
        }
        int fe = (part == 7) ? 63 : f0 + 8;
        for (int f = f0; f < fe; f++) {
            float a = 0.f;
#pragma unroll
            for (int k = 0; k < OBS; k++) a = fmaf(nf[k], s1_Wee[f * OBS + k], a);
            g_c[b][node][f] = a;
        }
        if (part == 7) g_c[b][node][63] = 0.f;

        __syncthreads();
        if (tid == 0) {
            float m = s1_cnt[0];
            for (int t = 1; t < 32; t++) m = fmaxf(m, s1_cnt[t]);
            g_blkmax[blk] = m;
        }
    }
    gbar_global();   // bmax is cross-batch; also publishes g_c / g_cur[0] / g_norm

    // ================= P1: edge aggregation + edge_emb (own 32-node tile) =================
    {
        float* s2_c   = sm;           // 8192
        float* s2_adj = sm + 8192;    // 4096 [32][128]
        float* s2_WT  = sm + 12288;   // 4160 [k][f] stride 65
        float* s2_x   = sm + 16448;   // 2048 [32][64]
        float* s2_w0  = sm + 18496;   // 64
        float* s2_mx  = sm + 18560;   // 1

        {
            const float4* src4 = (const float4*)&g_c[b][0][0];
            float4* dst4 = (float4*)s2_c;
            for (int t = tid; t < 2048; t += 256) dst4[t] = src4[t];
        }
        for (int t = tid; t < 4096; t += 256) {
            int n = t >> 7, j = t & 127;
            s2_adj[t] = ob[(i0 + n) * DW + OBS + j];
        }
        for (int t = tid; t < F * F; t += 256) {
            int ff = t >> 6, k = t & 63;
            s2_WT[k * 65 + ff] = Wef[t];
        }
        if (tid < F) s2_w0[tid] = (tid < 63) ? Wee[tid * 8] : 0.f;
        if (tid < 128) s2_x[tid] = g_blkmax[tid];   // temp reduce buffer
        __syncthreads();
        if (tid == 0) {
            float m = s2_x[0];
            for (int t = 1; t < 128; t++) m = fmaxf(m, s2_x[t]);
            s2_mx[0] = m;
        }
        __syncthreads();
        float mx = s2_mx[0];
        __syncthreads();   // all read mx before s2_x reuse

        int f = tid & 63, q = tid >> 6;
        float w0 = s2_w0[f];
        for (int n = q; n < 32; n += 4) {
            float s = 0.f;
            const float* arow = &s2_adj[n * 128];
#pragma unroll 8
            for (int j = 0; j < NN; j++) {
                float a = arow[j];
                float e = fmaxf(fmaf(a, w0, s2_c[j * 64 + f]), 0.f);
                s += (a != 0.f) ? e : 0.f;
            }
            float nrm = g_norm[b][i0 + n];
            s2_x[n * 64 + f] = (f < 63) ? (s / nrm) : (nrm / mx);
        }
        __syncthreads();
        for (int n = q; n < 32; n += 4) {
            float acc = 0.f;
#pragma unroll 8
            for (int k = 0; k < F; k++)
                acc = fmaf(s2_x[n * 64 + k], s2_WT[k * 65 + f], acc);
            g_edge[b][i0 + n][f] = fmaxf(acc, 0.f);
        }
        __syncthreads();   // edge is consumed only by this block — no global barrier
    }

    // ================= P2-P4: three message-passing layers =================
    {
        int fg = tid & 15;
        int ns = tid >> 4;
        int il0 = ns * 2, il1 = il0 + 1;

        for (int l = 0; l < 3; l++) {
            const float* Wl = Wm + l * 8192;
            const float* Ul = Wu + l * 8192;
            int src = (l == 1) ? 1 : 0;
            int dst = (l == 1) ? 0 : 1;

            for (int t = tid; t < 8192; t += 256) {
                int ff = t >> 7, k = t & 127;
                s_Wm[k * 68 + ff] = Wl[t];
                s_Wu[k * 68 + ff] = Ul[t];
            }
            {
                const float4* src4 = (const float4*)&g_cur[src][b][0][0];
                float4* dst4 = (float4*)s_cur;
                for (int t = tid; t < 2048; t += 256) dst4[t] = src4[t];
            }
            if (l == 0) {
                for (int t = tid; t < 4096; t += 256) {
                    int r = t >> 7, j = t & 127;
                    s_adj[t] = ob[(i0 + r) * DW + OBS + j];
                }
                const float4* es = (const float4*)&g_edge[b][i0][0];
                float4* ed = (float4*)s_edge;
                for (int t = tid; t < 512; t += 256) ed[t] = es[t];
                if (tid < 32) s_inv[tid] = 1.0f / g_norm[b][i0 + tid];
            }
            __syncthreads();

            // ---- agg = adj @ cur / norm ----
            {
                float4 a0 = {0, 0, 0, 0}, a1 = {0, 0, 0, 0};
                const float* ar0 = &s_adj[il0 * 128];
                const float* ar1 = &s_adj[il1 * 128];
#pragma unroll 8
                for (int j = 0; j < NN; j++) {
                    float4 c = *(const float4*)&s_cur[j * 64 + fg * 4];
                    float v0 = ar0[j], v1 = ar1[j];
                    a0.x = fmaf(v0, c.x, a0.x); a0.y = fmaf(v0, c.y, a0.y);
                    a0.z = fmaf(v0, c.z, a0.z); a0.w = fmaf(v0, c.w, a0.w);
                    a1.x = fmaf(v1, c.x, a1.x); a1.y = fmaf(v1, c.y, a1.y);
                    a1.z = fmaf(v1, c.z, a1.z); a1.w = fmaf(v1, c.w, a1.w);
                }
                float i0v = s_inv[il0], i1v = s_inv[il1];
                a0.x *= i0v; a0.y *= i0v; a0.z *= i0v; a0.w *= i0v;
                a1.x *= i1v; a1.y *= i1v; a1.z *= i1v; a1.w *= i1v;
                *(float4*)&s_agg[il0 * 64 + fg * 4] = a0;
                *(float4*)&s_agg[il1 * 64 + fg * 4] = a1;
            }
            __syncthreads();

            // ---- msg = relu([agg, edge] @ Wm^T) ----
            {
                float4 m0 = {0, 0, 0, 0}, m1 = {0, 0, 0, 0};
#pragma unroll 8
                for (int k = 0; k < F; k++) {
                    float4 w1 = *(const float4*)&s_Wm[k * 68 + fg * 4];
                    float4 w2 = *(const float4*)&s_Wm[(F + k) * 68 + fg * 4];
                    float g0 = s_agg[il0 * 64 + k], g1 = s_agg[il1 * 64 + k];
                    float e0 = s_edge[il0 * 64 + k], e1 = s_edge[il1 * 64 + k];
                    m0.x = fmaf(g0, w1.x, fmaf(e0, w2.x, m0.x));
                    m0.y = fmaf(g0, w1.y, fmaf(e0, w2.y, m0.y));
                    m0.z = fmaf(g0, w1.z, fmaf(e0, w2.z, m0.z));
                    m0.w = fmaf(g0, w1.w, fmaf(e0, w2.w, m0.w));
                    m1.x = fmaf(g1, w1.x, fmaf(e1, w2.x, m1.x));
                    m1.y = fmaf(g1, w1.y, fmaf(e1, w2.y, m1.y));
                    m1.z = fmaf(g1, w1.z, fmaf(e1, w2.z, m1.z));
                    m1.w = fmaf(g1, w1.w, fmaf(e1, w2.w, m1.w));
                }
                m0.x = fmaxf(m0.x, 0.f); m0.y = fmaxf(m0.y, 0.f);
                m0.z = fmaxf(m0.z, 0.f); m0.w = fmaxf(m0.w, 0.f);
                m1.x = fmaxf(m1.x, 0.f); m1.y = fmaxf(m1.y, 0.f);
                m1.z = fmaxf(m1.z, 0.f); m1.w = fmaxf(m1.w, 0.f);
                *(float4*)&s_msg[il0 * 64 + fg * 4] = m0;
                *(float4*)&s_msg[il1 * 64 + fg * 4] = m1;
            }
            __syncthreads();

            // ---- cur' = relu([cur, msg] @ Wu^T) ----
            {
                float4 u0 = {0, 0, 0, 0}, u1 = {0, 0, 0, 0};
                const float* c0 = &s_cur[(i0 + il0) * 64];
                const float* c1 = &s_cur[(i0 + il1) * 64];
#pragma unroll 8
                for (int k = 0; k < F; k++) {
                    float4 w1 = *(const float4*)&s_Wu[k * 68 + fg * 4];
                    float4 w2 = *(const float4*)&s_Wu[(F + k) * 68 + fg * 4];
                    float cv0 = c0[k], cv1 = c1[k];
                    float mv0 = s_msg[il0 * 64 + k], mv1 = s_msg[il1 * 64 + k];
                    u0.x = fmaf(cv0, w1.x, fmaf(mv0, w2.x, u0.x));
                    u0.y = fmaf(cv0, w1.y, fmaf(mv0, w2.y, u0.y));
                    u0.z = fmaf(cv0, w1.z, fmaf(mv0, w2.z, u0.z));
                    u0.w = fmaf(cv0, w1.w, fmaf(mv0, w2.w, u0.w));
                    u1.x = fmaf(cv1, w1.x, fmaf(mv1, w2.x, u1.x));
                    u1.y = fmaf(cv1, w1.y, fmaf(mv1, w2.y, u1.y));
                    u1.z = fmaf(cv1, w1.z, fmaf(mv1, w2.z, u1.z));
                    u1.w = fmaf(cv1, w1.w, fmaf(mv1, w2.w, u1.w));
                }
                u0.x = fmaxf(u0.x, 0.f); u0.y = fmaxf(u0.y, 0.f);
                u0.z = fmaxf(u0.z, 0.f); u0.w = fmaxf(u0.w, 0.f);
                u1.x = fmaxf(u1.x, 0.f); u1.y = fmaxf(u1.y, 0.f);
                u1.z = fmaxf(u1.z, 0.f); u1.w = fmaxf(u1.w, 0.f);
                *(float4*)&g_cur[dst][b][i0 + il0][fg * 4] = u0;
                *(float4*)&g_cur[dst][b][i0 + il1][fg * 4] = u1;
            }
            gbar_batch(b, l);   // only the 4 blocks of this batch need to sync
        }
    }

    // ================= P5: pool + readout precompute (all blocks; own 32 nodes) =================
    {
        float* s_part = sm;          // 256
        float* s_mean = sm + 256;    // 64
        float* s_rp   = sm + 320;    // 64
        float* s_P    = sm + 384;    // 4
        float* s_Wr   = sm + 388;    // 768

        for (int t = tid; t < OD * 3 * F; t += 256) s_Wr[t] = Wr[t];
        {
            int f = tid & 63, h = tid >> 6;
            float acc = 0.f;
            for (int i = h; i < NN; i += 4) acc += g_cur[1][b][i][f];
            s_part[tid] = acc;
        }
        __syncthreads();
        if (tid < F)
            s_mean[tid] = (s_part[tid] + s_part[tid + 64] + s_part[tid + 128] + s_part[tid + 192]) * (1.0f / NN);
        __syncthreads();
        if (tid < F) {
            float hp = 0.f;
#pragma unroll 8
            for (int k = 0; k < F; k++) hp = fmaf(s_mean[k], Wp[tid * 64 + k], hp);
            s_rp[tid] = fmaxf(hp, 0.f);
        }
        __syncthreads();
        if (tid < OD) {
            float p = br[tid];
#pragma unroll 8
            for (int f = 0; f < F; f++) p = fmaf(s_rp[f], s_Wr[tid * 192 + f], p);
            s_P[tid] = p;
        }
        __syncthreads();
        if (tid < 32) {
            int i = i0 + tid;
            float a[OD] = {0.f, 0.f, 0.f, 0.f};
            float c[OD] = {0.f, 0.f, 0.f, 0.f};
#pragma unroll 4
            for (int k = 0; k < F; k++) {
                float r = fmaxf(g_cur[1][b][i][k], 0.f);
#pragma unroll
                for (int o = 0; o < OD; o++) {
                    a[o] = fmaf(r, s_Wr[o * 192 + 64 + k], a[o]);
                    c[o] = fmaf(r, s_Wr[o * 192 + 128 + k], c[o]);
                }
            }
#pragma unroll
            for (int o = 0; o < OD; o++) {
                g_A[b][i][o] = a[o] + s_P[o];   // fold P into A
                g_C[b][i][o] = c[o];
            }
        }
    }
    gbar_batch(b, 3);   // g_C from sibling blocks needed below

    // ================= P6: output writer (own 32 i-rows) =================
    {
        int j = tid & 127;
        int ih = tid >> 7;   // 0..1
        float4 Cv = *(const float4*)&g_C[b][j][0];
        float4* out4 = (float4*)out;
#pragma unroll
        for (int ii = 0; ii < 16; ii++) {
            int i = i0 + ih * 16 + ii;
            float4 Av = *(const float4*)&g_A[b][i][0];
            float4 r;
            r.x = Av.x + Cv.x;
            r.y = Av.y + Cv.y;
            r.z = Av.z + Cv.z;
            r.w = Av.w + Cv.w;
            out4[((size_t)b * NN + i) * NN + j] = r;
        }
    }
}

// ---------------- launch ----------------
extern "C" void kernel_launch(void* const* d_in, const int* in_sizes, int n_in,
                              void* d_out, int out_size) {
    const float* obs = (const float*)d_in[0];
    const float* Wi  = (const float*)d_in[1];
    const float* Wee = (const float*)d_in[2];
    const float* Wef = (const float*)d_in[3];
    const float* Wm  = (const float*)d_in[4];
    const float* Wu  = (const float*)d_in[5];
    const float* Wp  = (const float*)d_in[6];
    const float* Wr  = (const float*)d_in[7];
    const float* br  = (const float*)d_in[8];

    static int attr_done = 0;
    if (!attr_done) {
        cudaFuncSetAttribute(mega, cudaFuncAttributeMaxDynamicSharedMemorySize, SM_BYTES);
        attr_done = 1;
    }

    mega<<<128, 256, SM_BYTES>>>(obs, Wi, Wee, Wef, Wm, Wu, Wp, Wr, br, (float*)d_out);
}